// round 3
// baseline (speedup 1.0000x reference)
#include <cuda_runtime.h>
#include <math.h>

// Problem constants
#define Bb 2
#define Sq 2048
#define Dm 1024
#define Hn 16
#define Hd 64

// ---------------- scratch (static device globals: no allocation allowed) ----
__device__ float g_q[Bb * Hn * Sq * Hd];     // [B,H,S,d], pre-scaled by 1/8
__device__ float g_k[Bb * Hn * Sq * Hd];     // [B,H,S,d]
__device__ float g_v[Bb * Hn * Sq * Hd];     // [B,H,S,d]
__device__ float g_att[Bb * Sq * Dm];        // [B,S,H*d] attention output pre-Wo
__device__ unsigned char g_bucket[4096];     // bucket LUT for rp = k - q in [-2047,2047]

// ---------------- T5 relative position bucket ------------------------------
__device__ __forceinline__ int rel_bucket(int rp) {
    // num_buckets=32 -> halved to 16; max_exact=8; max_distance=128
    int ret = (rp >= 0) ? 16 : 0;
    int n = rp < 0 ? -rp : rp;
    if (n < 8) return ret + n;
    // log(n/8)/log(16)*8, truncated toward zero (value >= 0 so trunc == floor)
    float v = logf((float)n * 0.125f) / logf(16.0f) * 8.0f;
    int vi = 8 + (int)v;
    if (vi > 15) vi = 15;
    return ret + vi;
}

__global__ void lut_kernel() {
    int i = blockIdx.x * 256 + threadIdx.x;   // 0..4095
    if (i < 4096) g_bucket[i] = (unsigned char)rel_bucket(i - 2047);
}

// past_bias writer: out layout [1,H,S,S] at d_out + B*S*D
__global__ void bias_kernel(const float* __restrict__ relb, float* __restrict__ out) {
    int q = blockIdx.x;
    int h = blockIdx.y;
    int k0 = threadIdx.x * 4;                 // 512 threads cover 2048 keys
    int lb = k0 - q + 2047;
    float4 v;
    v.x = relb[(int)g_bucket[lb + 0] * Hn + h];
    v.y = relb[(int)g_bucket[lb + 1] * Hn + h];
    v.z = relb[(int)g_bucket[lb + 2] * Hn + h];
    v.w = relb[(int)g_bucket[lb + 3] * Hn + h];
    *(float4*)(out + ((size_t)h * Sq + q) * Sq + k0) = v;
}

// ---------------- SGEMM: C[M,N] = A[M,K] @ W[N,K]^T -------------------------
// M=4096, N=1024, K=1024. Tile 128x64x16, 256 threads, 8x4 micro-tile.
// csel: 0/1/2 -> scatter to g_q/g_k/g_v as [B,H,S,d]; 3 -> row-major to Cext.
// asel: 0 -> Aext; 1 -> g_att.
#define GBM 128
#define GBN 64
#define GBK 16

__global__ __launch_bounds__(256)
void sgemm_kernel(const float* __restrict__ Aext, const float* __restrict__ W,
                  float* __restrict__ Cext, int asel, int csel, float scale) {
    const int Kdim = 1024;
    __shared__ float As[GBK][GBM + 4];
    __shared__ float Bs[GBK][GBN + 4];

    const float* A = asel ? g_att : Aext;
    const int tid = threadIdx.x;
    const int tx = tid & 15;   // n direction (16)
    const int ty = tid >> 4;   // m direction (16)
    const int bx = blockIdx.x; // N/64 = 16
    const int by = blockIdx.y; // M/128 = 32

    const float* Ab = A + (size_t)by * GBM * Kdim;
    const float* Wb = W + (size_t)bx * GBN * Kdim;

    float acc[8][4];
#pragma unroll
    for (int i = 0; i < 8; i++)
#pragma unroll
        for (int j = 0; j < 4; j++) acc[i][j] = 0.0f;

    const int lr = tid >> 2;         // 0..63
    const int lc = (tid & 3) * 4;    // 0,4,8,12

    for (int kt = 0; kt < Kdim; kt += GBK) {
        // Load A tile 128x16 (2 passes of 64 rows), transpose into As[k][m]
#pragma unroll
        for (int p = 0; p < 2; p++) {
            int r = lr + p * 64;
            float4 v = *(const float4*)(Ab + (size_t)r * Kdim + kt + lc);
            As[lc + 0][r] = v.x; As[lc + 1][r] = v.y;
            As[lc + 2][r] = v.z; As[lc + 3][r] = v.w;
        }
        // Load W tile 64x16, transpose into Bs[k][n]
        {
            float4 v = *(const float4*)(Wb + (size_t)lr * Kdim + kt + lc);
            Bs[lc + 0][lr] = v.x; Bs[lc + 1][lr] = v.y;
            Bs[lc + 2][lr] = v.z; Bs[lc + 3][lr] = v.w;
        }
        __syncthreads();

#pragma unroll
        for (int k = 0; k < GBK; k++) {
            float a[8], bf[4];
#pragma unroll
            for (int i = 0; i < 8; i++) a[i] = As[k][ty * 8 + i];
#pragma unroll
            for (int j = 0; j < 4; j++) bf[j] = Bs[k][tx * 4 + j];
#pragma unroll
            for (int i = 0; i < 8; i++)
#pragma unroll
                for (int j = 0; j < 4; j++) acc[i][j] += a[i] * bf[j];
        }
        __syncthreads();
    }

#pragma unroll
    for (int i = 0; i < 8; i++) {
        int m = by * GBM + ty * 8 + i;
#pragma unroll
        for (int j = 0; j < 4; j++) {
            int n = bx * GBN + tx * 4 + j;
            float val = acc[i][j] * scale;
            if (csel == 3) {
                Cext[(size_t)m * 1024 + n] = val;
            } else {
                float* C = (csel == 0) ? g_q : (csel == 1 ? g_k : g_v);
                int bbi = m >> 11, ssi = m & 2047;   // m = b*2048 + s
                int hhi = n >> 6,  ddi = n & 63;     // n = h*64 + d
                C[((((size_t)bbi * Hn + hhi) * Sq) + ssi) * Hd + ddi] = val;
            }
        }
    }
}

// ---------------- Flash attention: one query per thread ---------------------
// Block: 128 threads = 128 queries. Grid: (S/128, H, B).
// Q row (64f) and O accumulator (64f) live in registers; K/V tiles (64x64)
// staged in smem, read as warp-uniform LDS.128 broadcasts. Online softmax in
// chunks of 8 keys. Bias via bucket LUT + per-head rel_bias row in smem.
__global__ __launch_bounds__(128, 2)
void attn_kernel(const float* __restrict__ relb) {
    __shared__ float Ks[64][64];
    __shared__ float Vs[64][64];
    __shared__ float rb[32];
    __shared__ unsigned char lut[4096];

    const int tid = threadIdx.x;
    const int h = blockIdx.y, b = blockIdx.z;
    const int q = blockIdx.x * 128 + tid;

    for (int i = tid; i < 4096; i += 128) lut[i] = g_bucket[i];
    if (tid < 32) rb[tid] = relb[tid * Hn + h];

    const size_t bh = (size_t)(b * Hn + h) * Sq;
    const float* qrow = g_q + (bh + (size_t)q) * Hd;   // already scaled by 1/8
    float qr[64];
#pragma unroll
    for (int i = 0; i < 16; i++) {
        float4 v = ((const float4*)qrow)[i];
        qr[i * 4 + 0] = v.x; qr[i * 4 + 1] = v.y;
        qr[i * 4 + 2] = v.z; qr[i * 4 + 3] = v.w;
    }
    float o[64];
#pragma unroll
    for (int i = 0; i < 64; i++) o[i] = 0.0f;
    float mrun = -1e30f, lrun = 0.0f;

    const float* Kb = g_k + bh * Hd;
    const float* Vb = g_v + bh * Hd;

    for (int kt = 0; kt < Sq; kt += 64) {
        __syncthreads();   // also covers initial lut/rb visibility
#pragma unroll
        for (int p = 0; p < 8; p++) {
            int r = (tid >> 4) + p * 8;
            int c = (tid & 15) * 4;
            *(float4*)&Ks[r][c] = *(const float4*)(Kb + (size_t)(kt + r) * Hd + c);
            *(float4*)&Vs[r][c] = *(const float4*)(Vb + (size_t)(kt + r) * Hd + c);
        }
        __syncthreads();

#pragma unroll 1
        for (int ck = 0; ck < 64; ck += 8) {
            float s[8];
#pragma unroll
            for (int kk = 0; kk < 8; kk++) s[kk] = 0.0f;
#pragma unroll
            for (int d4 = 0; d4 < 16; d4++) {
#pragma unroll
                for (int kk = 0; kk < 8; kk++) {
                    float4 kv = *(const float4*)&Ks[ck + kk][d4 * 4];
                    s[kk] += qr[d4 * 4 + 0] * kv.x;
                    s[kk] += qr[d4 * 4 + 1] * kv.y;
                    s[kk] += qr[d4 * 4 + 2] * kv.z;
                    s[kk] += qr[d4 * 4 + 3] * kv.w;
                }
            }
            int lbase = kt + ck - q + 2047;
#pragma unroll
            for (int kk = 0; kk < 8; kk++) s[kk] += rb[lut[lbase + kk]];

            float cmax = s[0];
#pragma unroll
            for (int kk = 1; kk < 8; kk++) cmax = fmaxf(cmax, s[kk]);
            if (cmax > mrun) {
                float sc = __expf(mrun - cmax);
                mrun = cmax;
                lrun *= sc;
#pragma unroll
                for (int i = 0; i < 64; i++) o[i] *= sc;
            }
#pragma unroll
            for (int kk = 0; kk < 8; kk++) {
                s[kk] = __expf(s[kk] - mrun);
                lrun += s[kk];
            }
#pragma unroll
            for (int d4 = 0; d4 < 16; d4++) {
#pragma unroll
                for (int kk = 0; kk < 8; kk++) {
                    float4 vv = *(const float4*)&Vs[ck + kk][d4 * 4];
                    o[d4 * 4 + 0] += s[kk] * vv.x;
                    o[d4 * 4 + 1] += s[kk] * vv.y;
                    o[d4 * 4 + 2] += s[kk] * vv.z;
                    o[d4 * 4 + 3] += s[kk] * vv.w;
                }
            }
        }
    }

    float inv = 1.0f / lrun;
    float* orow = g_att + ((size_t)b * Sq + q) * Dm + h * Hd;
#pragma unroll
    for (int i = 0; i < 16; i++) {
        float4 v;
        v.x = o[i * 4 + 0] * inv; v.y = o[i * 4 + 1] * inv;
        v.z = o[i * 4 + 2] * inv; v.w = o[i * 4 + 3] * inv;
        ((float4*)orow)[i] = v;
    }
}

// ---------------- launch -----------------------------------------------------
extern "C" void kernel_launch(void* const* d_in, const int* in_sizes, int n_in,
                              void* d_out, int out_size) {
    (void)in_sizes; (void)n_in; (void)out_size;
    const float* x  = (const float*)d_in[0];
    const float* wq = (const float*)d_in[1];
    const float* wk = (const float*)d_in[2];
    const float* wv = (const float*)d_in[3];
    const float* wo = (const float*)d_in[4];
    const float* rb = (const float*)d_in[5];
    float* out = (float*)d_out;

    // 1. bucket LUT
    lut_kernel<<<16, 256>>>();
    // 2. past_bias -> second output region [1,H,S,S]
    bias_kernel<<<dim3(Sq, Hn), 512>>>(rb, out + (size_t)Bb * Sq * Dm);
    // 3. Q/K/V projections (Q fused with 1/sqrt(64) scale), scattered to [B,H,S,d]
    dim3 gg(Dm / GBN, (Bb * Sq) / GBM);   // (16, 32)
    sgemm_kernel<<<gg, 256>>>(x, wq, nullptr, 0, 0, 0.125f);
    sgemm_kernel<<<gg, 256>>>(x, wk, nullptr, 0, 1, 1.0f);
    sgemm_kernel<<<gg, 256>>>(x, wv, nullptr, 0, 2, 1.0f);
    // 4. flash attention with fused relative-position bias -> g_att [B,S,H*d]
    attn_kernel<<<dim3(Sq / 128, Hn, Bb), 128>>>(rb);
    // 5. output projection -> first output region [B,S,D]
    sgemm_kernel<<<gg, 256>>>(nullptr, wo, out, 1, 3, 1.0f);
}

// round 4
// speedup vs baseline: 1.0004x; 1.0004x over previous
#include <cuda_runtime.h>
#include <math.h>

// Problem constants
#define Bb 2
#define Sq 2048
#define Dm 1024
#define Hn 16
#define Hd 64

// ---------------- scratch (static device globals: no allocation allowed) ----
__device__ float g_q[Bb * Hn * Sq * Hd];     // [B,H,S,d], pre-scaled by 1/8
__device__ float g_k[Bb * Hn * Sq * Hd];     // [B,H,S,d]
__device__ float g_v[Bb * Hn * Sq * Hd];     // [B,H,S,d]
__device__ float g_att[Bb * Sq * Dm];        // [B,S,H*d] attention output pre-Wo
__device__ unsigned char g_bucket[4096];     // bucket LUT for rp = k - q in [-2047,2047]

// ---------------- T5 relative position bucket ------------------------------
__device__ __forceinline__ int rel_bucket(int rp) {
    // num_buckets=32 -> halved to 16; max_exact=8; max_distance=128
    int ret = (rp >= 0) ? 16 : 0;
    int n = rp < 0 ? -rp : rp;
    if (n < 8) return ret + n;
    // log(n/8)/log(16)*8, truncated toward zero (value >= 0 so trunc == floor)
    float v = logf((float)n * 0.125f) / logf(16.0f) * 8.0f;
    int vi = 8 + (int)v;
    if (vi > 15) vi = 15;
    return ret + vi;
}

__global__ void lut_kernel() {
    int i = blockIdx.x * 256 + threadIdx.x;   // 0..4095
    if (i < 4096) g_bucket[i] = (unsigned char)rel_bucket(i - 2047);
}

// past_bias writer: out layout [1,H,S,S] at d_out + B*S*D
__global__ void bias_kernel(const float* __restrict__ relb, float* __restrict__ out) {
    int q = blockIdx.x;
    int h = blockIdx.y;
    int k0 = threadIdx.x * 4;                 // 512 threads cover 2048 keys
    int lb = k0 - q + 2047;
    float4 v;
    v.x = relb[(int)g_bucket[lb + 0] * Hn + h];
    v.y = relb[(int)g_bucket[lb + 1] * Hn + h];
    v.z = relb[(int)g_bucket[lb + 2] * Hn + h];
    v.w = relb[(int)g_bucket[lb + 3] * Hn + h];
    *(float4*)(out + ((size_t)h * Sq + q) * Sq + k0) = v;
}

// ---------------- SGEMM: C[M,N] = A[M,K] @ W[N,K]^T -------------------------
// M=4096, N=1024, K=1024. Tile 128x64x16, 256 threads, 8x4 micro-tile.
// csel: 0/1/2 -> scatter to g_q/g_k/g_v as [B,H,S,d]; 3 -> row-major to Cext.
// asel: 0 -> Aext; 1 -> g_att.
#define GBM 128
#define GBN 64
#define GBK 16

__global__ __launch_bounds__(256)
void sgemm_kernel(const float* __restrict__ Aext, const float* __restrict__ W,
                  float* __restrict__ Cext, int asel, int csel, float scale) {
    const int Kdim = 1024;
    __shared__ float As[GBK][GBM + 4];
    __shared__ float Bs[GBK][GBN + 4];

    const float* A = asel ? g_att : Aext;
    const int tid = threadIdx.x;
    const int tx = tid & 15;   // n direction (16)
    const int ty = tid >> 4;   // m direction (16)
    const int bx = blockIdx.x; // N/64 = 16
    const int by = blockIdx.y; // M/128 = 32

    const float* Ab = A + (size_t)by * GBM * Kdim;
    const float* Wb = W + (size_t)bx * GBN * Kdim;

    float acc[8][4];
#pragma unroll
    for (int i = 0; i < 8; i++)
#pragma unroll
        for (int j = 0; j < 4; j++) acc[i][j] = 0.0f;

    const int lr = tid >> 2;         // 0..63
    const int lc = (tid & 3) * 4;    // 0,4,8,12

    for (int kt = 0; kt < Kdim; kt += GBK) {
        // Load A tile 128x16 (2 passes of 64 rows), transpose into As[k][m]
#pragma unroll
        for (int p = 0; p < 2; p++) {
            int r = lr + p * 64;
            float4 v = *(const float4*)(Ab + (size_t)r * Kdim + kt + lc);
            As[lc + 0][r] = v.x; As[lc + 1][r] = v.y;
            As[lc + 2][r] = v.z; As[lc + 3][r] = v.w;
        }
        // Load W tile 64x16, transpose into Bs[k][n]
        {
            float4 v = *(const float4*)(Wb + (size_t)lr * Kdim + kt + lc);
            Bs[lc + 0][lr] = v.x; Bs[lc + 1][lr] = v.y;
            Bs[lc + 2][lr] = v.z; Bs[lc + 3][lr] = v.w;
        }
        __syncthreads();

#pragma unroll
        for (int k = 0; k < GBK; k++) {
            float a[8], bf[4];
#pragma unroll
            for (int i = 0; i < 8; i++) a[i] = As[k][ty * 8 + i];
#pragma unroll
            for (int j = 0; j < 4; j++) bf[j] = Bs[k][tx * 4 + j];
#pragma unroll
            for (int i = 0; i < 8; i++)
#pragma unroll
                for (int j = 0; j < 4; j++) acc[i][j] += a[i] * bf[j];
        }
        __syncthreads();
    }

#pragma unroll
    for (int i = 0; i < 8; i++) {
        int m = by * GBM + ty * 8 + i;
#pragma unroll
        for (int j = 0; j < 4; j++) {
            int n = bx * GBN + tx * 4 + j;
            float val = acc[i][j] * scale;
            if (csel == 3) {
                Cext[(size_t)m * 1024 + n] = val;
            } else {
                float* C = (csel == 0) ? g_q : (csel == 1 ? g_k : g_v);
                int bbi = m >> 11, ssi = m & 2047;   // m = b*2048 + s
                int hhi = n >> 6,  ddi = n & 63;     // n = h*64 + d
                C[((((size_t)bbi * Hn + hhi) * Sq) + ssi) * Hd + ddi] = val;
            }
        }
    }
}

// ---------------- Flash attention: one query per thread ---------------------
// Block: 128 threads = 128 queries. Grid: (S/128, H, B).
// Q row (64f) and O accumulator (64f) live in registers; K/V tiles (64x64)
// staged in smem, read as warp-uniform LDS.128 broadcasts. Online softmax in
// chunks of 8 keys. Bias via bucket LUT + per-head rel_bias row in smem.
__global__ __launch_bounds__(128, 2)
void attn_kernel(const float* __restrict__ relb) {
    __shared__ float Ks[64][64];
    __shared__ float Vs[64][64];
    __shared__ float rb[32];
    __shared__ unsigned char lut[4096];

    const int tid = threadIdx.x;
    const int h = blockIdx.y, b = blockIdx.z;
    const int q = blockIdx.x * 128 + tid;

    for (int i = tid; i < 4096; i += 128) lut[i] = g_bucket[i];
    if (tid < 32) rb[tid] = relb[tid * Hn + h];

    const size_t bh = (size_t)(b * Hn + h) * Sq;
    const float* qrow = g_q + (bh + (size_t)q) * Hd;   // already scaled by 1/8
    float qr[64];
#pragma unroll
    for (int i = 0; i < 16; i++) {
        float4 v = ((const float4*)qrow)[i];
        qr[i * 4 + 0] = v.x; qr[i * 4 + 1] = v.y;
        qr[i * 4 + 2] = v.z; qr[i * 4 + 3] = v.w;
    }
    float o[64];
#pragma unroll
    for (int i = 0; i < 64; i++) o[i] = 0.0f;
    float mrun = -1e30f, lrun = 0.0f;

    const float* Kb = g_k + bh * Hd;
    const float* Vb = g_v + bh * Hd;

    for (int kt = 0; kt < Sq; kt += 64) {
        __syncthreads();   // also covers initial lut/rb visibility
#pragma unroll
        for (int p = 0; p < 8; p++) {
            int r = (tid >> 4) + p * 8;
            int c = (tid & 15) * 4;
            *(float4*)&Ks[r][c] = *(const float4*)(Kb + (size_t)(kt + r) * Hd + c);
            *(float4*)&Vs[r][c] = *(const float4*)(Vb + (size_t)(kt + r) * Hd + c);
        }
        __syncthreads();

#pragma unroll 1
        for (int ck = 0; ck < 64; ck += 8) {
            float s[8];
#pragma unroll
            for (int kk = 0; kk < 8; kk++) s[kk] = 0.0f;
#pragma unroll
            for (int d4 = 0; d4 < 16; d4++) {
#pragma unroll
                for (int kk = 0; kk < 8; kk++) {
                    float4 kv = *(const float4*)&Ks[ck + kk][d4 * 4];
                    s[kk] += qr[d4 * 4 + 0] * kv.x;
                    s[kk] += qr[d4 * 4 + 1] * kv.y;
                    s[kk] += qr[d4 * 4 + 2] * kv.z;
                    s[kk] += qr[d4 * 4 + 3] * kv.w;
                }
            }
            int lbase = kt + ck - q + 2047;
#pragma unroll
            for (int kk = 0; kk < 8; kk++) s[kk] += rb[lut[lbase + kk]];

            float cmax = s[0];
#pragma unroll
            for (int kk = 1; kk < 8; kk++) cmax = fmaxf(cmax, s[kk]);
            if (cmax > mrun) {
                float sc = __expf(mrun - cmax);
                mrun = cmax;
                lrun *= sc;
#pragma unroll
                for (int i = 0; i < 64; i++) o[i] *= sc;
            }
#pragma unroll
            for (int kk = 0; kk < 8; kk++) {
                s[kk] = __expf(s[kk] - mrun);
                lrun += s[kk];
            }
#pragma unroll
            for (int d4 = 0; d4 < 16; d4++) {
#pragma unroll
                for (int kk = 0; kk < 8; kk++) {
                    float4 vv = *(const float4*)&Vs[ck + kk][d4 * 4];
                    o[d4 * 4 + 0] += s[kk] * vv.x;
                    o[d4 * 4 + 1] += s[kk] * vv.y;
                    o[d4 * 4 + 2] += s[kk] * vv.z;
                    o[d4 * 4 + 3] += s[kk] * vv.w;
                }
            }
        }
    }

    float inv = 1.0f / lrun;
    float* orow = g_att + ((size_t)b * Sq + q) * Dm + h * Hd;
#pragma unroll
    for (int i = 0; i < 16; i++) {
        float4 v;
        v.x = o[i * 4 + 0] * inv; v.y = o[i * 4 + 1] * inv;
        v.z = o[i * 4 + 2] * inv; v.w = o[i * 4 + 3] * inv;
        ((float4*)orow)[i] = v;
    }
}

// ---------------- launch -----------------------------------------------------
extern "C" void kernel_launch(void* const* d_in, const int* in_sizes, int n_in,
                              void* d_out, int out_size) {
    (void)in_sizes; (void)n_in; (void)out_size;
    const float* x  = (const float*)d_in[0];
    const float* wq = (const float*)d_in[1];
    const float* wk = (const float*)d_in[2];
    const float* wv = (const float*)d_in[3];
    const float* wo = (const float*)d_in[4];
    const float* rb = (const float*)d_in[5];
    float* out = (float*)d_out;

    // 1. bucket LUT
    lut_kernel<<<16, 256>>>();
    // 2. past_bias -> second output region [1,H,S,S]
    bias_kernel<<<dim3(Sq, Hn), 512>>>(rb, out + (size_t)Bb * Sq * Dm);
    // 3. Q/K/V projections (Q fused with 1/sqrt(64) scale), scattered to [B,H,S,d]
    dim3 gg(Dm / GBN, (Bb * Sq) / GBM);   // (16, 32)
    sgemm_kernel<<<gg, 256>>>(x, wq, nullptr, 0, 0, 0.125f);
    sgemm_kernel<<<gg, 256>>>(x, wk, nullptr, 0, 1, 1.0f);
    sgemm_kernel<<<gg, 256>>>(x, wv, nullptr, 0, 2, 1.0f);
    // 4. flash attention with fused relative-position bias -> g_att [B,S,H*d]
    attn_kernel<<<dim3(Sq / 128, Hn, Bb), 128>>>(rb);
    // 5. output projection -> first output region [B,S,D]
    sgemm_kernel<<<gg, 256>>>(nullptr, wo, out, 1, 3, 1.0f);
}